// round 7
// baseline (speedup 1.0000x reference)
#include <cuda_runtime.h>
#include <cuda_fp16.h>
#include <math.h>

#define NN   50000
#define EE   800000
#define H_   64
#define GD   256   // HEADS*H
#define NBLK 196   // ceil(NN/256)

// ---------------- scratch (static device arrays; no allocation) ----------------
__device__ float  g_h0[NN * H_];     // x @ W_gcn
__device__ float  g_h [NN * H_];     // GCN output (relu)
__device__ __half g_gh[NN * GD];     // h @ W_gat (fp16 storage)
__device__ float  g_g2[NN * GD];     // GAT output (relu)
__device__ float  g_yr[NN * 128];    // [g2@Wl | g2@Wr]
__device__ float  g_s [NN * H_];     // SAGE output
__device__ float  g_uv[NN * 128];    // [u | v] per node
__device__ float  g_w1p[64 * 128];   // packed W1
__device__ float  g_wsp[256 * 128];  // packed [W_sage_l | W_sage_r]
__device__ float  g_as[NN * 4];      // attention src logits
__device__ float  g_ad[NN * 4];      // attention dst logits
__device__ float  g_dinv[NN];        // rsqrt(deg+1)
__device__ int    g_cnt[NN];         // in-degree (no self loop)
__device__ int    g_cur[NN];         // fill cursor
__device__ int    g_rs [NN + 1];     // CSR row starts (by dst)
__device__ int    g_bsum[NBLK];      // block sums for scan
__device__ int    g_csrc[EE];        // CSR: src node per slot

__device__ __forceinline__ float lrelu(float x) { return x > 0.f ? x : 0.2f * x; }

// ---------------- CSR build ----------------
__global__ void init_kernel(int* __restrict__ cnt, int* __restrict__ cur) {
    int i = blockIdx.x * blockDim.x + threadIdx.x;
    if (i < NN) { cnt[i] = 0; cur[i] = 0; }
}

__global__ void hist_kernel(const int* __restrict__ dst, int* __restrict__ cnt) {
    int e = blockIdx.x * blockDim.x + threadIdx.x;
    if (e * 4 < EE) {
        int4 d = ((const int4*)dst)[e];
        atomicAdd(&cnt[d.x], 1); atomicAdd(&cnt[d.y], 1);
        atomicAdd(&cnt[d.z], 1); atomicAdd(&cnt[d.w], 1);
    }
}

__global__ void blocksum_kernel(const int* __restrict__ cnt, int* __restrict__ bsum) {
    __shared__ int ws[8];
    int i = blockIdx.x * 256 + threadIdx.x;
    int v = (i < NN) ? cnt[i] : 0;
    #pragma unroll
    for (int off = 16; off; off >>= 1) v += __shfl_down_sync(0xffffffffu, v, off);
    if ((threadIdx.x & 31) == 0) ws[threadIdx.x >> 5] = v;
    __syncthreads();
    if (threadIdx.x < 8) {
        int t = ws[threadIdx.x];
        #pragma unroll
        for (int off = 4; off; off >>= 1) t += __shfl_down_sync(0xffu, t, off);
        if (threadIdx.x == 0) bsum[blockIdx.x] = t;
    }
}

__global__ void scanb_kernel(int* __restrict__ bsum) {
    __shared__ int buf[256];
    int tid = threadIdx.x;
    int v = (tid < NBLK) ? bsum[tid] : 0;
    buf[tid] = v;
    __syncthreads();
    #pragma unroll
    for (int off = 1; off < 256; off <<= 1) {
        int t = (tid >= off) ? buf[tid - off] : 0;
        __syncthreads();
        buf[tid] += t;
        __syncthreads();
    }
    if (tid < NBLK) bsum[tid] = buf[tid] - v;  // exclusive
}

__global__ void rs_kernel(const int* __restrict__ cnt, const int* __restrict__ bsum,
                          int* __restrict__ rs, float* __restrict__ dinv) {
    __shared__ int buf[256];
    int tid = threadIdx.x;
    int i = blockIdx.x * 256 + tid;
    int v = (i < NN) ? cnt[i] : 0;
    buf[tid] = v;
    __syncthreads();
    #pragma unroll
    for (int off = 1; off < 256; off <<= 1) {
        int t = (tid >= off) ? buf[tid - off] : 0;
        __syncthreads();
        buf[tid] += t;
        __syncthreads();
    }
    if (i < NN) {
        rs[i] = bsum[blockIdx.x] + buf[tid] - v;
        dinv[i] = rsqrtf((float)(v + 1));
    }
    if (i == 0) rs[NN] = EE;
}

__global__ void fill_kernel(const int* __restrict__ src, const int* __restrict__ dst,
                            const int* __restrict__ rs, int* __restrict__ cur,
                            int* __restrict__ csrc) {
    int e = blockIdx.x * blockDim.x + threadIdx.x;
    if (e < EE) {
        int d = dst[e];
        int pos = atomicAdd(&cur[d], 1);
        csrc[rs[d] + pos] = src[e];
    }
}

// ---------------- tf32 tensor-core GEMM, smem-staged, fragment-major B ----------
// 256 threads (8 warps), tile 128 rows x 64 cols, K-panel 32.
// B stored fragment-major WsF[kk][g][12-pad] -> b-frags read as LDS.128
// (4 per k-step instead of 16 scalar LDS). Pad 12 => conflict-free banks.
__device__ __forceinline__ unsigned f2tf(float x) {
    unsigned r;
    asm("cvt.rna.tf32.f32 %0, %1;" : "=r"(r) : "f"(x));
    return r;
}

template <bool HALF_OUT>
__global__ __launch_bounds__(256, 3) void gemm_smem(
        const float* __restrict__ A, const float* __restrict__ W,
        void* __restrict__ Cv, int n, int K, int M) {
    __shared__ unsigned As[128][36];          // [row][k]
    __shared__ unsigned WsF[32 * 8 * 12];     // [kk][g][nt(12 pad)]
    int tid = threadIdx.x;
    int warp = tid >> 5, lane = tid & 31;
    int g = lane >> 2, t = lane & 3;
    int row0 = blockIdx.y * 128;
    int col0 = blockIdx.x * 64;

    float4 pa[4], pw[2];
    #pragma unroll
    for (int q = 0; q < 4; q++) {
        int j = tid + q * 256, r = row0 + (j >> 3), kq = j & 7;
        pa[q] = (r < n) ? *(const float4*)(A + (size_t)r * K + kq * 4)
                        : make_float4(0.f, 0.f, 0.f, 0.f);
    }
    #pragma unroll
    for (int q = 0; q < 2; q++) {
        int j = tid + q * 256, kk = j >> 4, cq = j & 15;
        pw[q] = *(const float4*)(W + (size_t)kk * M + col0 + cq * 4);
    }

    float acc[8][4];
    #pragma unroll
    for (int i = 0; i < 8; i++)
        #pragma unroll
        for (int j = 0; j < 4; j++) acc[i][j] = 0.f;

    int NP = K >> 5;
    for (int p = 0; p < NP; p++) {
        // deposit A (row-major, tf32 once)
        #pragma unroll
        for (int q = 0; q < 4; q++) {
            int j = tid + q * 256, r = j >> 3, kq = j & 7;
            uint4 u = make_uint4(f2tf(pa[q].x), f2tf(pa[q].y), f2tf(pa[q].z), f2tf(pa[q].w));
            *(uint4*)&As[r][kq * 4] = u;
        }
        // deposit W fragment-major: element (kk, c=cq*4+i) -> WsF[kk][c&7][c>>3]
        #pragma unroll
        for (int q = 0; q < 2; q++) {
            int j = tid + q * 256, kk = j >> 4, cq = j & 15;
            int g0 = (cq & 1) * 4, nt = cq >> 1;
            unsigned* base = &WsF[(kk * 8 + g0) * 12 + nt];
            base[0]      = f2tf(pw[q].x);
            base[12]     = f2tf(pw[q].y);
            base[24]     = f2tf(pw[q].z);
            base[36]     = f2tf(pw[q].w);
        }
        __syncthreads();

        // prefetch next panel
        if (p + 1 < NP) {
            int k0 = (p + 1) << 5;
            #pragma unroll
            for (int q = 0; q < 4; q++) {
                int j = tid + q * 256, r = row0 + (j >> 3), kq = j & 7;
                pa[q] = (r < n) ? *(const float4*)(A + (size_t)r * K + k0 + kq * 4)
                                : make_float4(0.f, 0.f, 0.f, 0.f);
            }
            #pragma unroll
            for (int q = 0; q < 2; q++) {
                int j = tid + q * 256, kk = j >> 4, cq = j & 15;
                pw[q] = *(const float4*)(W + (size_t)(k0 + kk) * M + col0 + cq * 4);
            }
        }

        int rb = warp << 4;
        #pragma unroll
        for (int ks = 0; ks < 4; ks++) {
            int kk = ks * 8 + t;
            unsigned a0 = As[rb + g][kk],     a1 = As[rb + g + 8][kk];
            unsigned a2 = As[rb + g][kk + 4], a3 = As[rb + g + 8][kk + 4];
            const unsigned* b0p = &WsF[(kk * 8 + g) * 12];
            const unsigned* b1p = &WsF[((kk + 4) * 8 + g) * 12];
            uint4 bA0 = *(const uint4*)(b0p);      // b0 for nt 0..3
            uint4 bA1 = *(const uint4*)(b0p + 4);  // b0 for nt 4..7
            uint4 bB0 = *(const uint4*)(b1p);      // b1 for nt 0..3
            uint4 bB1 = *(const uint4*)(b1p + 4);  // b1 for nt 4..7
            unsigned bs0[8] = {bA0.x, bA0.y, bA0.z, bA0.w, bA1.x, bA1.y, bA1.z, bA1.w};
            unsigned bs1[8] = {bB0.x, bB0.y, bB0.z, bB0.w, bB1.x, bB1.y, bB1.z, bB1.w};
            #pragma unroll
            for (int nt = 0; nt < 8; nt++) {
                asm("mma.sync.aligned.m16n8k8.row.col.f32.tf32.tf32.f32 "
                    "{%0,%1,%2,%3}, {%4,%5,%6,%7}, {%8,%9}, {%0,%1,%2,%3};"
                    : "+f"(acc[nt][0]), "+f"(acc[nt][1]), "+f"(acc[nt][2]), "+f"(acc[nt][3])
                    : "r"(a0), "r"(a1), "r"(a2), "r"(a3), "r"(bs0[nt]), "r"(bs1[nt]));
            }
        }
        __syncthreads();
    }

    int r0 = row0 + (warp << 4) + g, r1 = r0 + 8;
    #pragma unroll
    for (int nt = 0; nt < 8; nt++) {
        int c = col0 + nt * 8 + 2 * t;
        if (HALF_OUT) {
            __half2* C = (__half2*)Cv;
            if (r0 < n) C[((size_t)r0 * M + c) >> 1] = __floats2half2_rn(acc[nt][0], acc[nt][1]);
            if (r1 < n) C[((size_t)r1 * M + c) >> 1] = __floats2half2_rn(acc[nt][2], acc[nt][3]);
        } else {
            float* C = (float*)Cv;
            if (r0 < n) *(float2*)(C + (size_t)r0 * M + c) = make_float2(acc[nt][0], acc[nt][1]);
            if (r1 < n) *(float2*)(C + (size_t)r1 * M + c) = make_float2(acc[nt][2], acc[nt][3]);
        }
    }
}

// ---------------- pack W1 and [W_sage_l | W_sage_r] ----------------
__global__ void pack_kernel(const float* __restrict__ W1, const float* __restrict__ Wl,
                            const float* __restrict__ Wr, float* __restrict__ W1p,
                            float* __restrict__ Wsp) {
    int i = blockIdx.x * 256 + threadIdx.x;
    if (i < 64 * 128) {
        int k = i >> 7, m = i & 127;
        W1p[i] = (m < 64) ? W1[k * 64 + m] : W1[(64 + k) * 64 + (m - 64)];
    }
    int j = i - 64 * 128;
    if (j >= 0 && j < 256 * 128) {
        int k = j >> 7, m = j & 127;
        Wsp[j] = (m < 64) ? Wl[k * 64 + m] : Wr[k * 64 + (m - 64)];
    }
}

// ---------------- GCN aggregation (warp per node, float2 lanes) ----------------
__global__ void gcn_agg_kernel(const float* __restrict__ h0, const float* __restrict__ b_gcn,
                               const int* __restrict__ rs, const int* __restrict__ csrc,
                               const float* __restrict__ dinv, float* __restrict__ hout) {
    int node = (blockIdx.x * blockDim.x + threadIdx.x) >> 5;
    int lane = threadIdx.x & 31;
    if (node >= NN) return;
    int beg = rs[node], end = rs[node + 1];
    float dinv_d = dinv[node];
    const float2* H = (const float2*)h0;
    float ax = 0.f, ay = 0.f;
    for (int p = beg; p < end; p++) {
        int s = csrc[p];
        float ds = dinv[s];
        float2 hv = H[(size_t)s * 32 + lane];
        ax += hv.x * ds; ay += hv.y * ds;
    }
    float2 hd = H[(size_t)node * 32 + lane];
    ax = (ax + hd.x * dinv_d) * dinv_d;
    ay = (ay + hd.y * dinv_d) * dinv_d;
    float2 b = ((const float2*)b_gcn)[lane];
    float2 o;
    o.x = fmaxf(ax + b.x, 0.f);
    o.y = fmaxf(ay + b.y, 0.f);
    ((float2*)hout)[(size_t)node * 32 + lane] = o;
}

// ---------------- attention logits from fp16 g ----------------
__global__ void att_kernel(const __half* __restrict__ ghp,
                           const float* __restrict__ att_src,
                           const float* __restrict__ att_dst,
                           float* __restrict__ as_, float* __restrict__ ad_) {
    int node = (blockIdx.x * blockDim.x + threadIdx.x) >> 5;
    int lane = threadIdx.x & 31;
    if (node >= NN) return;
    const float4* GH = (const float4*)ghp;
    float4 raw = GH[(size_t)node * 32 + lane];
    const __half2* hp = (const __half2*)&raw;
    float4 wsa = ((const float4*)att_src)[2 * lane];
    float4 wsb = ((const float4*)att_src)[2 * lane + 1];
    float4 wda = ((const float4*)att_dst)[2 * lane];
    float4 wdb = ((const float4*)att_dst)[2 * lane + 1];
    float2 f0 = __half22float2(hp[0]), f1 = __half22float2(hp[1]);
    float2 f2 = __half22float2(hp[2]), f3 = __half22float2(hp[3]);
    float ps = f0.x * wsa.x + f0.y * wsa.y + f1.x * wsa.z + f1.y * wsa.w
             + f2.x * wsb.x + f2.y * wsb.y + f3.x * wsb.z + f3.y * wsb.w;
    float pd = f0.x * wda.x + f0.y * wda.y + f1.x * wda.z + f1.y * wda.w
             + f2.x * wdb.x + f2.y * wdb.y + f3.x * wdb.z + f3.y * wdb.w;
    #pragma unroll
    for (int off = 4; off; off >>= 1) {
        ps += __shfl_down_sync(0xffffffffu, ps, off, 8);
        pd += __shfl_down_sync(0xffffffffu, pd, off, 8);
    }
    if ((lane & 7) == 0) {
        int head = lane >> 3;
        as_[node * 4 + head] = ps;
        ad_[node * 4 + head] = pd;
    }
}

// ---------------- GAT aggregation (fp16 gather, fused softmax) ----------------
__global__ void gat_agg_kernel(const __half* __restrict__ ghp,
                               const float* __restrict__ as_,
                               const float* __restrict__ ad_,
                               const float* __restrict__ b_gat,
                               const int* __restrict__ rs,
                               const int* __restrict__ csrc,
                               float* __restrict__ g2) {
    int node = (blockIdx.x * blockDim.x + threadIdx.x) >> 5;
    int lane = threadIdx.x & 31;
    if (node >= NN) return;
    int beg = rs[node], end = rs[node + 1];
    float4 adv = *(const float4*)(ad_ + 4 * node);
    float4 asd = *(const float4*)(as_ + 4 * node);
    float e0s = lrelu(asd.x + adv.x), e1s = lrelu(asd.y + adv.y);
    float e2s = lrelu(asd.z + adv.z), e3s = lrelu(asd.w + adv.w);
    float m0 = e0s, m1 = e1s, m2 = e2s, m3 = e3s;
    for (int p = beg + lane; p < end; p += 32) {
        int s = csrc[p];
        float4 av = *(const float4*)(as_ + 4 * s);
        m0 = fmaxf(m0, lrelu(av.x + adv.x));
        m1 = fmaxf(m1, lrelu(av.y + adv.y));
        m2 = fmaxf(m2, lrelu(av.z + adv.z));
        m3 = fmaxf(m3, lrelu(av.w + adv.w));
    }
    #pragma unroll
    for (int off = 16; off; off >>= 1) {
        m0 = fmaxf(m0, __shfl_xor_sync(0xffffffffu, m0, off));
        m1 = fmaxf(m1, __shfl_xor_sync(0xffffffffu, m1, off));
        m2 = fmaxf(m2, __shfl_xor_sync(0xffffffffu, m2, off));
        m3 = fmaxf(m3, __shfl_xor_sync(0xffffffffu, m3, off));
    }
    int c = lane & 3;
    float adc = c == 0 ? adv.x : c == 1 ? adv.y : c == 2 ? adv.z : adv.w;
    float mc  = c == 0 ? m0    : c == 1 ? m1    : c == 2 ? m2    : m3;
    int head = lane >> 3;
    float acc[8] = {0.f, 0.f, 0.f, 0.f, 0.f, 0.f, 0.f, 0.f};
    float z0 = 0.f, z1 = 0.f, z2 = 0.f, z3 = 0.f;
    const float4* GH = (const float4*)ghp;
    for (int p = beg; p < end; p++) {
        int s = csrc[p];
        float4 av = *(const float4*)(as_ + 4 * s);
        float ac = c == 0 ? av.x : c == 1 ? av.y : c == 2 ? av.z : av.w;
        float wl = expf(lrelu(ac + adc) - mc);
        float w0 = __shfl_sync(0xffffffffu, wl, 0);
        float w1 = __shfl_sync(0xffffffffu, wl, 1);
        float w2 = __shfl_sync(0xffffffffu, wl, 2);
        float w3 = __shfl_sync(0xffffffffu, wl, 3);
        z0 += w0; z1 += w1; z2 += w2; z3 += w3;
        float w = head == 0 ? w0 : head == 1 ? w1 : head == 2 ? w2 : w3;
        float4 raw = GH[(size_t)s * 32 + lane];
        const __half2* hp = (const __half2*)&raw;
        #pragma unroll
        for (int j = 0; j < 4; j++) {
            float2 f = __half22float2(hp[j]);
            acc[2 * j]     += f.x * w;
            acc[2 * j + 1] += f.y * w;
        }
    }
    float w0s = expf(e0s - m0), w1s = expf(e1s - m1);
    float w2s = expf(e2s - m2), w3s = expf(e3s - m3);
    z0 += w0s; z1 += w1s; z2 += w2s; z3 += w3s;
    {
        float w = head == 0 ? w0s : head == 1 ? w1s : head == 2 ? w2s : w3s;
        float4 raw = GH[(size_t)node * 32 + lane];
        const __half2* hp = (const __half2*)&raw;
        #pragma unroll
        for (int j = 0; j < 4; j++) {
            float2 f = __half22float2(hp[j]);
            acc[2 * j]     += f.x * w;
            acc[2 * j + 1] += f.y * w;
        }
    }
    float zh = head == 0 ? z0 : head == 1 ? z1 : head == 2 ? z2 : z3;
    float inv = 1.f / (zh + 1e-16f);
    float4 ba = ((const float4*)b_gat)[2 * lane];
    float4 bb = ((const float4*)b_gat)[2 * lane + 1];
    float4 oa, ob;
    oa.x = fmaxf(acc[0] * inv + ba.x, 0.f);
    oa.y = fmaxf(acc[1] * inv + ba.y, 0.f);
    oa.z = fmaxf(acc[2] * inv + ba.z, 0.f);
    oa.w = fmaxf(acc[3] * inv + ba.w, 0.f);
    ob.x = fmaxf(acc[4] * inv + bb.x, 0.f);
    ob.y = fmaxf(acc[5] * inv + bb.y, 0.f);
    ob.z = fmaxf(acc[6] * inv + bb.z, 0.f);
    ob.w = fmaxf(acc[7] * inv + bb.w, 0.f);
    ((float4*)g2)[(size_t)node * 64 + 2 * lane]     = oa;
    ((float4*)g2)[(size_t)node * 64 + 2 * lane + 1] = ob;
}

// ---------------- SAGE fused: s = relu(sum(y[nbr])/cnt + r + b) ----------------
__global__ void sage_fuse_kernel(const float* __restrict__ yr,
                                 const float* __restrict__ b_sage,
                                 const int* __restrict__ rs, const int* __restrict__ csrc,
                                 float* __restrict__ s) {
    int node = (blockIdx.x * blockDim.x + threadIdx.x) >> 5;
    int lane = threadIdx.x & 31;
    if (node >= NN) return;
    int beg = rs[node], end = rs[node + 1];
    const float2* Y = (const float2*)yr;
    float ax = 0.f, ay = 0.f;
    for (int p = beg; p < end; p++) {
        int sn = csrc[p];
        float2 yv = Y[(size_t)sn * 64 + lane];
        ax += yv.x; ay += yv.y;
    }
    float inv = 1.f / fmaxf((float)(end - beg), 1.f);
    float2 rv = Y[(size_t)node * 64 + 32 + lane];
    float2 bv = ((const float2*)b_sage)[lane];
    float2 o;
    o.x = fmaxf(ax * inv + rv.x + bv.x, 0.f);
    o.y = fmaxf(ay * inv + rv.y + bv.y, 0.f);
    ((float2*)s)[(size_t)node * 32 + lane] = o;
}

// ---------------- edge MLP + sigmoid (16 lanes per edge) ----------------
__global__ void edge_kernel(const int* __restrict__ src, const int* __restrict__ dst,
                            const float* __restrict__ uv, const float* __restrict__ b1,
                            const float* __restrict__ W2, const float* __restrict__ b2,
                            float* __restrict__ out) {
    int idx = blockIdx.x * blockDim.x + threadIdx.x;
    int e = idx >> 4;
    int l = idx & 15;
    if (e >= EE) return;
    int si = src[e], di = dst[e];
    const float4* UV = (const float4*)uv;
    float4 uu = UV[(size_t)si * 32 + l];
    float4 vv = UV[(size_t)di * 32 + 16 + l];
    float4 bb = ((const float4*)b1)[l];
    float4 ww = ((const float4*)W2)[l];
    float p = fmaxf(uu.x + vv.x + bb.x, 0.f) * ww.x
            + fmaxf(uu.y + vv.y + bb.y, 0.f) * ww.y
            + fmaxf(uu.z + vv.z + bb.z, 0.f) * ww.z
            + fmaxf(uu.w + vv.w + bb.w, 0.f) * ww.w;
    #pragma unroll
    for (int off = 8; off; off >>= 1) p += __shfl_xor_sync(0xffffffffu, p, off);
    if (l == 0) out[e] = 1.f / (1.f + expf(-(p + b2[0])));
}

// ---------------- launch ----------------
extern "C" void kernel_launch(void* const* d_in, const int* in_sizes, int n_in,
                              void* d_out, int out_size) {
    const float* x        = (const float*)d_in[0];
    const int*   ei       = (const int*)  d_in[1];
    const float* W_gcn    = (const float*)d_in[2];
    const float* b_gcn    = (const float*)d_in[3];
    const float* W_gat    = (const float*)d_in[4];
    const float* att_src  = (const float*)d_in[5];
    const float* att_dst  = (const float*)d_in[6];
    const float* b_gat    = (const float*)d_in[7];
    const float* W_sage_l = (const float*)d_in[8];
    const float* b_sage   = (const float*)d_in[9];
    const float* W_sage_r = (const float*)d_in[10];
    const float* W1       = (const float*)d_in[11];
    const float* b1       = (const float*)d_in[12];
    const float* W2       = (const float*)d_in[13];
    const float* b2       = (const float*)d_in[14];
    float* out = (float*)d_out;
    const int* src = ei;
    const int* dst = ei + EE;

    float *h0, *h, *g2, *yr, *s, *uv, *w1p, *wsp, *as_, *ad_, *dinv;
    __half* gh;
    int *cnt, *cur, *rs, *bsum, *csrc;
    cudaGetSymbolAddress((void**)&h0,  g_h0);
    cudaGetSymbolAddress((void**)&h,   g_h);
    cudaGetSymbolAddress((void**)&gh,  g_gh);
    cudaGetSymbolAddress((void**)&g2,  g_g2);
    cudaGetSymbolAddress((void**)&yr,  g_yr);
    cudaGetSymbolAddress((void**)&s,   g_s);
    cudaGetSymbolAddress((void**)&uv,  g_uv);
    cudaGetSymbolAddress((void**)&w1p, g_w1p);
    cudaGetSymbolAddress((void**)&wsp, g_wsp);
    cudaGetSymbolAddress((void**)&as_, g_as);
    cudaGetSymbolAddress((void**)&ad_, g_ad);
    cudaGetSymbolAddress((void**)&dinv, g_dinv);
    cudaGetSymbolAddress((void**)&cnt, g_cnt);
    cudaGetSymbolAddress((void**)&cur, g_cur);
    cudaGetSymbolAddress((void**)&rs,  g_rs);
    cudaGetSymbolAddress((void**)&bsum, g_bsum);
    cudaGetSymbolAddress((void**)&csrc, g_csrc);

    const int NB_NODE = (NN + 255) / 256;          // 196
    const int NB_EDGE = (EE + 255) / 256;          // 3125
    const int NB_E4   = (EE / 4 + 255) / 256;      // 782
    const int NB_NW   = (NN * 32 + 255) / 256;     // 6250
    const int NB_E16  = (EE * 16 + 255) / 256;     // 50000
    const int NT128   = (NN + 127) / 128;          // 391

    // 1-3: CSR counts (GEMM placed 4th so the profiler slot lands on it)
    init_kernel<<<NB_NODE, 256>>>(cnt, cur);
    hist_kernel<<<NB_E4, 256>>>(dst, cnt);
    blocksum_kernel<<<NBLK, 256>>>(cnt, bsum);
    // 4: GCN GEMM (profiled slot)
    gemm_smem<false><<<dim3(1, NT128), 256>>>(x, W_gcn, h0, NN, 128, 64);
    // 5-8: finish CSR + packs
    scanb_kernel<<<1, 256>>>(bsum);
    rs_kernel<<<NBLK, 256>>>(cnt, bsum, rs, dinv);
    fill_kernel<<<NB_EDGE, 256>>>(src, dst, rs, cur, csrc);
    pack_kernel<<<(64 * 128 + 256 * 128 + 255) / 256, 256>>>(W1, W_sage_l, W_sage_r, w1p, wsp);

    // GCN aggregate
    gcn_agg_kernel<<<NB_NW, 256>>>(h0, b_gcn, rs, csrc, dinv, h);

    // GAT (fp16 g)
    gemm_smem<true><<<dim3(4, NT128), 256>>>(h, W_gat, gh, NN, 64, 256);
    att_kernel<<<NB_NW, 256>>>(gh, att_src, att_dst, as_, ad_);
    gat_agg_kernel<<<NB_NW, 256>>>(gh, as_, ad_, b_gat, rs, csrc, g2);

    // SAGE: yr = g2 @ [Wl | Wr], then fused gather
    gemm_smem<false><<<dim3(2, NT128), 256>>>(g2, wsp, yr, NN, 256, 128);
    sage_fuse_kernel<<<NB_NW, 256>>>(yr, b_sage, rs, csrc, s);

    // edge MLP: uv = s @ W1p
    gemm_smem<false><<<dim3(2, NT128), 256>>>(s, w1p, uv, NN, 64, 128);

    // per-edge: sigmoid(relu(u[src]+v[dst]+b1) . W2 + b2)
    edge_kernel<<<NB_E16, 256>>>(src, dst, uv, b1, W2, b2, out);
}

// round 8
// speedup vs baseline: 1.2167x; 1.2167x over previous
#include <cuda_runtime.h>
#include <cuda_fp16.h>
#include <math.h>

#define NN   50000
#define EE   800000
#define H_   64
#define GD   256   // HEADS*H
#define NBLK 196   // ceil(NN/256)

// ---------------- scratch (static device arrays; no allocation) ----------------
__device__ float  g_h0[NN * H_];     // x @ W_gcn
__device__ float  g_h [NN * H_];     // GCN output (relu)
__device__ __half g_gh[NN * GD];     // h @ W_gat (fp16 storage)
__device__ float  g_g2[NN * GD];     // GAT output (relu)
__device__ float  g_yr[NN * 128];    // [g2@Wl | g2@Wr]
__device__ float  g_s [NN * H_];     // SAGE output
__device__ __half g_uvh[NN * 128];   // [u | v] per node (fp16)
__device__ float  g_w1p[64 * 128];   // packed W1
__device__ float  g_wsp[256 * 128];  // packed [W_sage_l | W_sage_r]
__device__ float  g_as[NN * 4];      // attention src logits
__device__ float  g_ad[NN * 4];      // attention dst logits
__device__ float  g_dinv[NN];        // rsqrt(deg+1)
__device__ int    g_cnt[NN];         // in-degree (no self loop)
__device__ int    g_cur[NN];         // fill cursor
__device__ int    g_rs [NN + 1];     // CSR row starts (by dst)
__device__ int    g_bsum[NBLK];      // block sums for scan
__device__ int    g_csrc[EE];        // CSR: src node per slot

__device__ __forceinline__ float lrelu(float x) { return x > 0.f ? x : 0.2f * x; }

// ---------------- CSR build ----------------
__global__ void init_kernel(int* __restrict__ cnt, int* __restrict__ cur) {
    int i = blockIdx.x * blockDim.x + threadIdx.x;
    if (i < NN) { cnt[i] = 0; cur[i] = 0; }
}

__global__ void hist_kernel(const int* __restrict__ dst, int* __restrict__ cnt) {
    int e = blockIdx.x * blockDim.x + threadIdx.x;
    if (e * 4 < EE) {
        int4 d = ((const int4*)dst)[e];
        atomicAdd(&cnt[d.x], 1); atomicAdd(&cnt[d.y], 1);
        atomicAdd(&cnt[d.z], 1); atomicAdd(&cnt[d.w], 1);
    }
}

__global__ void blocksum_kernel(const int* __restrict__ cnt, int* __restrict__ bsum) {
    __shared__ int ws[8];
    int i = blockIdx.x * 256 + threadIdx.x;
    int v = (i < NN) ? cnt[i] : 0;
    #pragma unroll
    for (int off = 16; off; off >>= 1) v += __shfl_down_sync(0xffffffffu, v, off);
    if ((threadIdx.x & 31) == 0) ws[threadIdx.x >> 5] = v;
    __syncthreads();
    if (threadIdx.x < 8) {
        int t = ws[threadIdx.x];
        #pragma unroll
        for (int off = 4; off; off >>= 1) t += __shfl_down_sync(0xffu, t, off);
        if (threadIdx.x == 0) bsum[blockIdx.x] = t;
    }
}

__global__ void scanb_kernel(int* __restrict__ bsum) {
    __shared__ int buf[256];
    int tid = threadIdx.x;
    int v = (tid < NBLK) ? bsum[tid] : 0;
    buf[tid] = v;
    __syncthreads();
    #pragma unroll
    for (int off = 1; off < 256; off <<= 1) {
        int t = (tid >= off) ? buf[tid - off] : 0;
        __syncthreads();
        buf[tid] += t;
        __syncthreads();
    }
    if (tid < NBLK) bsum[tid] = buf[tid] - v;  // exclusive
}

__global__ void rs_kernel(const int* __restrict__ cnt, const int* __restrict__ bsum,
                          int* __restrict__ rs, float* __restrict__ dinv) {
    __shared__ int buf[256];
    int tid = threadIdx.x;
    int i = blockIdx.x * 256 + tid;
    int v = (i < NN) ? cnt[i] : 0;
    buf[tid] = v;
    __syncthreads();
    #pragma unroll
    for (int off = 1; off < 256; off <<= 1) {
        int t = (tid >= off) ? buf[tid - off] : 0;
        __syncthreads();
        buf[tid] += t;
        __syncthreads();
    }
    if (i < NN) {
        rs[i] = bsum[blockIdx.x] + buf[tid] - v;
        dinv[i] = rsqrtf((float)(v + 1));
    }
    if (i == 0) rs[NN] = EE;
}

__global__ void fill_kernel(const int* __restrict__ src, const int* __restrict__ dst,
                            const int* __restrict__ rs, int* __restrict__ cur,
                            int* __restrict__ csrc) {
    int e = blockIdx.x * blockDim.x + threadIdx.x;
    if (e < EE) {
        int d = dst[e];
        int pos = atomicAdd(&cur[d], 1);
        csrc[rs[d] + pos] = src[e];
    }
}

// ---------------- tf32 tensor-core GEMM, smem-staged (R6 known-good) ----------
__device__ __forceinline__ unsigned f2tf(float x) {
    unsigned r;
    asm("cvt.rna.tf32.f32 %0, %1;" : "=r"(r) : "f"(x));
    return r;
}

template <bool HALF_OUT>
__global__ __launch_bounds__(256) void gemm_smem(
        const float* __restrict__ A, const float* __restrict__ W,
        void* __restrict__ Cv, int n, int K, int M) {
    __shared__ unsigned As[128][36];
    __shared__ unsigned Ws[32][72];
    int tid = threadIdx.x;
    int warp = tid >> 5, lane = tid & 31;
    int g = lane >> 2, t = lane & 3;
    int row0 = blockIdx.y * 128;
    int col0 = blockIdx.x * 64;

    float4 pa[4], pw[2];
    #pragma unroll
    for (int q = 0; q < 4; q++) {
        int j = tid + q * 256, r = row0 + (j >> 3), kq = j & 7;
        pa[q] = (r < n) ? *(const float4*)(A + (size_t)r * K + kq * 4)
                        : make_float4(0.f, 0.f, 0.f, 0.f);
    }
    #pragma unroll
    for (int q = 0; q < 2; q++) {
        int j = tid + q * 256, kk = j >> 4, cq = j & 15;
        pw[q] = *(const float4*)(W + (size_t)kk * M + col0 + cq * 4);
    }

    float acc[8][4];
    #pragma unroll
    for (int i = 0; i < 8; i++)
        #pragma unroll
        for (int j = 0; j < 4; j++) acc[i][j] = 0.f;

    int NP = K >> 5;
    for (int p = 0; p < NP; p++) {
        #pragma unroll
        for (int q = 0; q < 4; q++) {
            int j = tid + q * 256, r = j >> 3, kq = j & 7;
            uint4 u = make_uint4(f2tf(pa[q].x), f2tf(pa[q].y), f2tf(pa[q].z), f2tf(pa[q].w));
            *(uint4*)&As[r][kq * 4] = u;
        }
        #pragma unroll
        for (int q = 0; q < 2; q++) {
            int j = tid + q * 256, kk = j >> 4, cq = j & 15;
            uint4 u = make_uint4(f2tf(pw[q].x), f2tf(pw[q].y), f2tf(pw[q].z), f2tf(pw[q].w));
            *(uint4*)&Ws[kk][cq * 4] = u;
        }
        __syncthreads();

        if (p + 1 < NP) {
            int k0 = (p + 1) << 5;
            #pragma unroll
            for (int q = 0; q < 4; q++) {
                int j = tid + q * 256, r = row0 + (j >> 3), kq = j & 7;
                pa[q] = (r < n) ? *(const float4*)(A + (size_t)r * K + k0 + kq * 4)
                                : make_float4(0.f, 0.f, 0.f, 0.f);
            }
            #pragma unroll
            for (int q = 0; q < 2; q++) {
                int j = tid + q * 256, kk = j >> 4, cq = j & 15;
                pw[q] = *(const float4*)(W + (size_t)(k0 + kk) * M + col0 + cq * 4);
            }
        }

        int rb = warp << 4;
        #pragma unroll
        for (int ks = 0; ks < 4; ks++) {
            int kk = ks * 8 + t;
            unsigned a0 = As[rb + g][kk],     a1 = As[rb + g + 8][kk];
            unsigned a2 = As[rb + g][kk + 4], a3 = As[rb + g + 8][kk + 4];
            #pragma unroll
            for (int nt = 0; nt < 8; nt++) {
                unsigned b0 = Ws[kk][nt * 8 + g];
                unsigned b1 = Ws[kk + 4][nt * 8 + g];
                asm("mma.sync.aligned.m16n8k8.row.col.f32.tf32.tf32.f32 "
                    "{%0,%1,%2,%3}, {%4,%5,%6,%7}, {%8,%9}, {%0,%1,%2,%3};"
                    : "+f"(acc[nt][0]), "+f"(acc[nt][1]), "+f"(acc[nt][2]), "+f"(acc[nt][3])
                    : "r"(a0), "r"(a1), "r"(a2), "r"(a3), "r"(b0), "r"(b1));
            }
        }
        __syncthreads();
    }

    int r0 = row0 + (warp << 4) + g, r1 = r0 + 8;
    #pragma unroll
    for (int nt = 0; nt < 8; nt++) {
        int c = col0 + nt * 8 + 2 * t;
        if (HALF_OUT) {
            __half2* C = (__half2*)Cv;
            if (r0 < n) C[((size_t)r0 * M + c) >> 1] = __floats2half2_rn(acc[nt][0], acc[nt][1]);
            if (r1 < n) C[((size_t)r1 * M + c) >> 1] = __floats2half2_rn(acc[nt][2], acc[nt][3]);
        } else {
            float* C = (float*)Cv;
            if (r0 < n) *(float2*)(C + (size_t)r0 * M + c) = make_float2(acc[nt][0], acc[nt][1]);
            if (r1 < n) *(float2*)(C + (size_t)r1 * M + c) = make_float2(acc[nt][2], acc[nt][3]);
        }
    }
}

// ---------------- pack W1 and [W_sage_l | W_sage_r] ----------------
__global__ void pack_kernel(const float* __restrict__ W1, const float* __restrict__ Wl,
                            const float* __restrict__ Wr, float* __restrict__ W1p,
                            float* __restrict__ Wsp) {
    int i = blockIdx.x * 256 + threadIdx.x;
    if (i < 64 * 128) {
        int k = i >> 7, m = i & 127;
        W1p[i] = (m < 64) ? W1[k * 64 + m] : W1[(64 + k) * 64 + (m - 64)];
    }
    int j = i - 64 * 128;
    if (j >= 0 && j < 256 * 128) {
        int k = j >> 7, m = j & 127;
        Wsp[j] = (m < 64) ? Wl[k * 64 + m] : Wr[k * 64 + (m - 64)];
    }
}

// ---------------- GCN aggregation (warp per node, float2 lanes) ----------------
__global__ void gcn_agg_kernel(const float* __restrict__ h0, const float* __restrict__ b_gcn,
                               const int* __restrict__ rs, const int* __restrict__ csrc,
                               const float* __restrict__ dinv, float* __restrict__ hout) {
    int node = (blockIdx.x * blockDim.x + threadIdx.x) >> 5;
    int lane = threadIdx.x & 31;
    if (node >= NN) return;
    int beg = rs[node], end = rs[node + 1];
    float dinv_d = dinv[node];
    const float2* H = (const float2*)h0;
    float ax = 0.f, ay = 0.f;
    for (int p = beg; p < end; p++) {
        int s = csrc[p];
        float ds = dinv[s];
        float2 hv = H[(size_t)s * 32 + lane];
        ax += hv.x * ds; ay += hv.y * ds;
    }
    float2 hd = H[(size_t)node * 32 + lane];
    ax = (ax + hd.x * dinv_d) * dinv_d;
    ay = (ay + hd.y * dinv_d) * dinv_d;
    float2 b = ((const float2*)b_gcn)[lane];
    float2 o;
    o.x = fmaxf(ax + b.x, 0.f);
    o.y = fmaxf(ay + b.y, 0.f);
    ((float2*)hout)[(size_t)node * 32 + lane] = o;
}

// ---------------- attention logits from fp16 g ----------------
__global__ void att_kernel(const __half* __restrict__ ghp,
                           const float* __restrict__ att_src,
                           const float* __restrict__ att_dst,
                           float* __restrict__ as_, float* __restrict__ ad_) {
    int node = (blockIdx.x * blockDim.x + threadIdx.x) >> 5;
    int lane = threadIdx.x & 31;
    if (node >= NN) return;
    const float4* GH = (const float4*)ghp;
    float4 raw = GH[(size_t)node * 32 + lane];
    const __half2* hp = (const __half2*)&raw;
    float4 wsa = ((const float4*)att_src)[2 * lane];
    float4 wsb = ((const float4*)att_src)[2 * lane + 1];
    float4 wda = ((const float4*)att_dst)[2 * lane];
    float4 wdb = ((const float4*)att_dst)[2 * lane + 1];
    float2 f0 = __half22float2(hp[0]), f1 = __half22float2(hp[1]);
    float2 f2 = __half22float2(hp[2]), f3 = __half22float2(hp[3]);
    float ps = f0.x * wsa.x + f0.y * wsa.y + f1.x * wsa.z + f1.y * wsa.w
             + f2.x * wsb.x + f2.y * wsb.y + f3.x * wsb.z + f3.y * wsb.w;
    float pd = f0.x * wda.x + f0.y * wda.y + f1.x * wda.z + f1.y * wda.w
             + f2.x * wdb.x + f2.y * wdb.y + f3.x * wdb.z + f3.y * wdb.w;
    #pragma unroll
    for (int off = 4; off; off >>= 1) {
        ps += __shfl_down_sync(0xffffffffu, ps, off, 8);
        pd += __shfl_down_sync(0xffffffffu, pd, off, 8);
    }
    if ((lane & 7) == 0) {
        int head = lane >> 3;
        as_[node * 4 + head] = ps;
        ad_[node * 4 + head] = pd;
    }
}

// ---------------- GAT aggregation (fp16 gather, fused softmax) ----------------
__global__ void gat_agg_kernel(const __half* __restrict__ ghp,
                               const float* __restrict__ as_,
                               const float* __restrict__ ad_,
                               const float* __restrict__ b_gat,
                               const int* __restrict__ rs,
                               const int* __restrict__ csrc,
                               float* __restrict__ g2) {
    int node = (blockIdx.x * blockDim.x + threadIdx.x) >> 5;
    int lane = threadIdx.x & 31;
    if (node >= NN) return;
    int beg = rs[node], end = rs[node + 1];
    float4 adv = *(const float4*)(ad_ + 4 * node);
    float4 asd = *(const float4*)(as_ + 4 * node);
    float e0s = lrelu(asd.x + adv.x), e1s = lrelu(asd.y + adv.y);
    float e2s = lrelu(asd.z + adv.z), e3s = lrelu(asd.w + adv.w);
    float m0 = e0s, m1 = e1s, m2 = e2s, m3 = e3s;
    for (int p = beg + lane; p < end; p += 32) {
        int s = csrc[p];
        float4 av = *(const float4*)(as_ + 4 * s);
        m0 = fmaxf(m0, lrelu(av.x + adv.x));
        m1 = fmaxf(m1, lrelu(av.y + adv.y));
        m2 = fmaxf(m2, lrelu(av.z + adv.z));
        m3 = fmaxf(m3, lrelu(av.w + adv.w));
    }
    #pragma unroll
    for (int off = 16; off; off >>= 1) {
        m0 = fmaxf(m0, __shfl_xor_sync(0xffffffffu, m0, off));
        m1 = fmaxf(m1, __shfl_xor_sync(0xffffffffu, m1, off));
        m2 = fmaxf(m2, __shfl_xor_sync(0xffffffffu, m2, off));
        m3 = fmaxf(m3, __shfl_xor_sync(0xffffffffu, m3, off));
    }
    int c = lane & 3;
    float adc = c == 0 ? adv.x : c == 1 ? adv.y : c == 2 ? adv.z : adv.w;
    float mc  = c == 0 ? m0    : c == 1 ? m1    : c == 2 ? m2    : m3;
    int head = lane >> 3;
    float acc[8] = {0.f, 0.f, 0.f, 0.f, 0.f, 0.f, 0.f, 0.f};
    float z0 = 0.f, z1 = 0.f, z2 = 0.f, z3 = 0.f;
    const float4* GH = (const float4*)ghp;
    for (int p = beg; p < end; p++) {
        int s = csrc[p];
        float4 av = *(const float4*)(as_ + 4 * s);
        float ac = c == 0 ? av.x : c == 1 ? av.y : c == 2 ? av.z : av.w;
        float wl = expf(lrelu(ac + adc) - mc);
        float w0 = __shfl_sync(0xffffffffu, wl, 0);
        float w1 = __shfl_sync(0xffffffffu, wl, 1);
        float w2 = __shfl_sync(0xffffffffu, wl, 2);
        float w3 = __shfl_sync(0xffffffffu, wl, 3);
        z0 += w0; z1 += w1; z2 += w2; z3 += w3;
        float w = head == 0 ? w0 : head == 1 ? w1 : head == 2 ? w2 : w3;
        float4 raw = GH[(size_t)s * 32 + lane];
        const __half2* hp = (const __half2*)&raw;
        #pragma unroll
        for (int j = 0; j < 4; j++) {
            float2 f = __half22float2(hp[j]);
            acc[2 * j]     += f.x * w;
            acc[2 * j + 1] += f.y * w;
        }
    }
    float w0s = expf(e0s - m0), w1s = expf(e1s - m1);
    float w2s = expf(e2s - m2), w3s = expf(e3s - m3);
    z0 += w0s; z1 += w1s; z2 += w2s; z3 += w3s;
    {
        float w = head == 0 ? w0s : head == 1 ? w1s : head == 2 ? w2s : w3s;
        float4 raw = GH[(size_t)node * 32 + lane];
        const __half2* hp = (const __half2*)&raw;
        #pragma unroll
        for (int j = 0; j < 4; j++) {
            float2 f = __half22float2(hp[j]);
            acc[2 * j]     += f.x * w;
            acc[2 * j + 1] += f.y * w;
        }
    }
    float zh = head == 0 ? z0 : head == 1 ? z1 : head == 2 ? z2 : z3;
    float inv = 1.f / (zh + 1e-16f);
    float4 ba = ((const float4*)b_gat)[2 * lane];
    float4 bb = ((const float4*)b_gat)[2 * lane + 1];
    float4 oa, ob;
    oa.x = fmaxf(acc[0] * inv + ba.x, 0.f);
    oa.y = fmaxf(acc[1] * inv + ba.y, 0.f);
    oa.z = fmaxf(acc[2] * inv + ba.z, 0.f);
    oa.w = fmaxf(acc[3] * inv + ba.w, 0.f);
    ob.x = fmaxf(acc[4] * inv + bb.x, 0.f);
    ob.y = fmaxf(acc[5] * inv + bb.y, 0.f);
    ob.z = fmaxf(acc[6] * inv + bb.z, 0.f);
    ob.w = fmaxf(acc[7] * inv + bb.w, 0.f);
    ((float4*)g2)[(size_t)node * 64 + 2 * lane]     = oa;
    ((float4*)g2)[(size_t)node * 64 + 2 * lane + 1] = ob;
}

// ---------------- SAGE fused: s = relu(sum(y[nbr])/cnt + r + b) ----------------
__global__ void sage_fuse_kernel(const float* __restrict__ yr,
                                 const float* __restrict__ b_sage,
                                 const int* __restrict__ rs, const int* __restrict__ csrc,
                                 float* __restrict__ s) {
    int node = (blockIdx.x * blockDim.x + threadIdx.x) >> 5;
    int lane = threadIdx.x & 31;
    if (node >= NN) return;
    int beg = rs[node], end = rs[node + 1];
    const float2* Y = (const float2*)yr;
    float ax = 0.f, ay = 0.f;
    for (int p = beg; p < end; p++) {
        int sn = csrc[p];
        float2 yv = Y[(size_t)sn * 64 + lane];
        ax += yv.x; ay += yv.y;
    }
    float inv = 1.f / fmaxf((float)(end - beg), 1.f);
    float2 rv = Y[(size_t)node * 64 + 32 + lane];
    float2 bv = ((const float2*)b_sage)[lane];
    float2 o;
    o.x = fmaxf(ax * inv + rv.x + bv.x, 0.f);
    o.y = fmaxf(ay * inv + rv.y + bv.y, 0.f);
    ((float2*)s)[(size_t)node * 32 + lane] = o;
}

// ---------------- edge MLP + sigmoid (16 lanes per edge, fp16 uv) ----------------
__global__ void edge_kernel(const int* __restrict__ src, const int* __restrict__ dst,
                            const __half* __restrict__ uvh, const float* __restrict__ b1,
                            const float* __restrict__ W2, const float* __restrict__ b2,
                            float* __restrict__ out) {
    int idx = blockIdx.x * blockDim.x + threadIdx.x;
    int e = idx >> 4;
    int l = idx & 15;
    if (e >= EE) return;
    int si = src[e], di = dst[e];
    const uint2* UV = (const uint2*)uvh;     // 4 halves per uint2; row = 32 uint2
    uint2 ur = UV[(size_t)si * 32 + l];
    uint2 vr = UV[(size_t)di * 32 + 16 + l];
    float2 u0 = __half22float2(*(const __half2*)&ur.x);
    float2 u1 = __half22float2(*(const __half2*)&ur.y);
    float2 v0 = __half22float2(*(const __half2*)&vr.x);
    float2 v1 = __half22float2(*(const __half2*)&vr.y);
    float4 bb = ((const float4*)b1)[l];
    float4 ww = ((const float4*)W2)[l];
    float p = fmaxf(u0.x + v0.x + bb.x, 0.f) * ww.x
            + fmaxf(u0.y + v0.y + bb.y, 0.f) * ww.y
            + fmaxf(u1.x + v1.x + bb.z, 0.f) * ww.z
            + fmaxf(u1.y + v1.y + bb.w, 0.f) * ww.w;
    #pragma unroll
    for (int off = 8; off; off >>= 1) p += __shfl_xor_sync(0xffffffffu, p, off);
    if (l == 0) out[e] = 1.f / (1.f + expf(-(p + b2[0])));
}

// ---------------- launch ----------------
extern "C" void kernel_launch(void* const* d_in, const int* in_sizes, int n_in,
                              void* d_out, int out_size) {
    const float* x        = (const float*)d_in[0];
    const int*   ei       = (const int*)  d_in[1];
    const float* W_gcn    = (const float*)d_in[2];
    const float* b_gcn    = (const float*)d_in[3];
    const float* W_gat    = (const float*)d_in[4];
    const float* att_src  = (const float*)d_in[5];
    const float* att_dst  = (const float*)d_in[6];
    const float* b_gat    = (const float*)d_in[7];
    const float* W_sage_l = (const float*)d_in[8];
    const float* b_sage   = (const float*)d_in[9];
    const float* W_sage_r = (const float*)d_in[10];
    const float* W1       = (const float*)d_in[11];
    const float* b1       = (const float*)d_in[12];
    const float* W2       = (const float*)d_in[13];
    const float* b2       = (const float*)d_in[14];
    float* out = (float*)d_out;
    const int* src = ei;
    const int* dst = ei + EE;

    float *h0, *h, *g2, *yr, *s, *w1p, *wsp, *as_, *ad_, *dinv;
    __half *gh, *uvh;
    int *cnt, *cur, *rs, *bsum, *csrc;
    cudaGetSymbolAddress((void**)&h0,  g_h0);
    cudaGetSymbolAddress((void**)&h,   g_h);
    cudaGetSymbolAddress((void**)&gh,  g_gh);
    cudaGetSymbolAddress((void**)&g2,  g_g2);
    cudaGetSymbolAddress((void**)&yr,  g_yr);
    cudaGetSymbolAddress((void**)&s,   g_s);
    cudaGetSymbolAddress((void**)&uvh, g_uvh);
    cudaGetSymbolAddress((void**)&w1p, g_w1p);
    cudaGetSymbolAddress((void**)&wsp, g_wsp);
    cudaGetSymbolAddress((void**)&as_, g_as);
    cudaGetSymbolAddress((void**)&ad_, g_ad);
    cudaGetSymbolAddress((void**)&dinv, g_dinv);
    cudaGetSymbolAddress((void**)&cnt, g_cnt);
    cudaGetSymbolAddress((void**)&cur, g_cur);
    cudaGetSymbolAddress((void**)&rs,  g_rs);
    cudaGetSymbolAddress((void**)&bsum, g_bsum);
    cudaGetSymbolAddress((void**)&csrc, g_csrc);

    const int NB_NODE = (NN + 255) / 256;          // 196
    const int NB_EDGE = (EE + 255) / 256;          // 3125
    const int NB_E4   = (EE / 4 + 255) / 256;      // 782
    const int NB_NW   = (NN * 32 + 255) / 256;     // 6250
    const int NB_E16  = (EE * 16 + 255) / 256;     // 50000
    const int NT128   = (NN + 127) / 128;          // 391

    // 1-3: CSR counts (GEMM placed 4th so the profiler slot lands on it)
    init_kernel<<<NB_NODE, 256>>>(cnt, cur);
    hist_kernel<<<NB_E4, 256>>>(dst, cnt);
    blocksum_kernel<<<NBLK, 256>>>(cnt, bsum);
    // 4: GCN GEMM (profiled control — expect ~15.3 us again after revert)
    gemm_smem<false><<<dim3(1, NT128), 256>>>(x, W_gcn, h0, NN, 128, 64);
    // 5-8: finish CSR + packs
    scanb_kernel<<<1, 256>>>(bsum);
    rs_kernel<<<NBLK, 256>>>(cnt, bsum, rs, dinv);
    fill_kernel<<<NB_EDGE, 256>>>(src, dst, rs, cur, csrc);
    pack_kernel<<<(64 * 128 + 256 * 128 + 255) / 256, 256>>>(W1, W_sage_l, W_sage_r, w1p, wsp);

    // GCN aggregate
    gcn_agg_kernel<<<NB_NW, 256>>>(h0, b_gcn, rs, csrc, dinv, h);

    // GAT (fp16 g)
    gemm_smem<true><<<dim3(4, NT128), 256>>>(h, W_gat, gh, NN, 64, 256);
    att_kernel<<<NB_NW, 256>>>(gh, att_src, att_dst, as_, ad_);
    gat_agg_kernel<<<NB_NW, 256>>>(gh, as_, ad_, b_gat, rs, csrc, g2);

    // SAGE: yr = g2 @ [Wl | Wr], then fused gather
    gemm_smem<false><<<dim3(2, NT128), 256>>>(g2, wsp, yr, NN, 256, 128);
    sage_fuse_kernel<<<NB_NW, 256>>>(yr, b_sage, rs, csrc, s);

    // edge MLP: uv = s @ W1p (fp16 out)
    gemm_smem<true><<<dim3(2, NT128), 256>>>(s, w1p, uvh, NN, 64, 128);

    // per-edge: sigmoid(relu(u[src]+v[dst]+b1) . W2 + b2)
    edge_kernel<<<NB_E16, 256>>>(src, dst, uvh, b1, W2, b2, out);
}

// round 9
// speedup vs baseline: 1.3358x; 1.0979x over previous
#include <cuda_runtime.h>
#include <cuda_fp16.h>
#include <math.h>

#define NN   50000
#define EE   800000
#define H_   64
#define GD   256   // HEADS*H
#define NBLK 196   // ceil(NN/256)

// ---------------- scratch (static device arrays; no allocation) ----------------
__device__ float  g_h0[NN * H_];     // x @ W_gcn
__device__ float  g_h [NN * H_];     // GCN output (relu)
__device__ __half g_gh[NN * GD];     // h @ W_gat (fp16 storage)
__device__ float  g_g2[NN * GD];     // GAT output (relu)
__device__ float  g_yr[NN * 128];    // [g2@Wl | g2@Wr]
__device__ float  g_s [NN * H_];     // SAGE output
__device__ float  g_uv[NN * 128];    // [u | v] per node (fp32 — fp16 regressed)
__device__ float  g_w1p[64 * 128];   // packed W1
__device__ float  g_wsp[256 * 128];  // packed [W_sage_l | W_sage_r]
__device__ float  g_as[NN * 4];      // attention src logits
__device__ float  g_ad[NN * 4];      // attention dst logits
__device__ float  g_alpha[EE * 4];   // unnormalized edge softmax weights (float4/edge)
__device__ float  g_wself[NN * 4];   // unnormalized self-loop weights
__device__ float  g_zinv[NN * 4];    // 1/(softmax denominator)
__device__ float  g_dinv[NN];        // rsqrt(deg+1)
__device__ int    g_cnt[NN];         // in-degree (no self loop)
__device__ int    g_cur[NN];         // fill cursor
__device__ int    g_rs [NN + 1];     // CSR row starts (by dst)
__device__ int    g_bsum[NBLK];      // block sums for scan
__device__ int    g_csrc[EE];        // CSR: src node per slot

__device__ __forceinline__ float lrelu(float x) { return x > 0.f ? x : 0.2f * x; }

// ---------------- CSR build ----------------
__global__ void init_kernel(int* __restrict__ cnt, int* __restrict__ cur) {
    int i = blockIdx.x * blockDim.x + threadIdx.x;
    if (i < NN) { cnt[i] = 0; cur[i] = 0; }
}

__global__ void hist_kernel(const int* __restrict__ dst, int* __restrict__ cnt) {
    int e = blockIdx.x * blockDim.x + threadIdx.x;
    if (e * 4 < EE) {
        int4 d = ((const int4*)dst)[e];
        atomicAdd(&cnt[d.x], 1); atomicAdd(&cnt[d.y], 1);
        atomicAdd(&cnt[d.z], 1); atomicAdd(&cnt[d.w], 1);
    }
}

__global__ void blocksum_kernel(const int* __restrict__ cnt, int* __restrict__ bsum) {
    __shared__ int ws[8];
    int i = blockIdx.x * 256 + threadIdx.x;
    int v = (i < NN) ? cnt[i] : 0;
    #pragma unroll
    for (int off = 16; off; off >>= 1) v += __shfl_down_sync(0xffffffffu, v, off);
    if ((threadIdx.x & 31) == 0) ws[threadIdx.x >> 5] = v;
    __syncthreads();
    if (threadIdx.x < 8) {
        int t = ws[threadIdx.x];
        #pragma unroll
        for (int off = 4; off; off >>= 1) t += __shfl_down_sync(0xffu, t, off);
        if (threadIdx.x == 0) bsum[blockIdx.x] = t;
    }
}

__global__ void scanb_kernel(int* __restrict__ bsum) {
    __shared__ int buf[256];
    int tid = threadIdx.x;
    int v = (tid < NBLK) ? bsum[tid] : 0;
    buf[tid] = v;
    __syncthreads();
    #pragma unroll
    for (int off = 1; off < 256; off <<= 1) {
        int t = (tid >= off) ? buf[tid - off] : 0;
        __syncthreads();
        buf[tid] += t;
        __syncthreads();
    }
    if (tid < NBLK) bsum[tid] = buf[tid] - v;  // exclusive
}

__global__ void rs_kernel(const int* __restrict__ cnt, const int* __restrict__ bsum,
                          int* __restrict__ rs, float* __restrict__ dinv) {
    __shared__ int buf[256];
    int tid = threadIdx.x;
    int i = blockIdx.x * 256 + tid;
    int v = (i < NN) ? cnt[i] : 0;
    buf[tid] = v;
    __syncthreads();
    #pragma unroll
    for (int off = 1; off < 256; off <<= 1) {
        int t = (tid >= off) ? buf[tid - off] : 0;
        __syncthreads();
        buf[tid] += t;
        __syncthreads();
    }
    if (i < NN) {
        rs[i] = bsum[blockIdx.x] + buf[tid] - v;
        dinv[i] = rsqrtf((float)(v + 1));
    }
    if (i == 0) rs[NN] = EE;
}

__global__ void fill_kernel(const int* __restrict__ src, const int* __restrict__ dst,
                            const int* __restrict__ rs, int* __restrict__ cur,
                            int* __restrict__ csrc) {
    int e = blockIdx.x * blockDim.x + threadIdx.x;
    if (e < EE) {
        int d = dst[e];
        int pos = atomicAdd(&cur[d], 1);
        csrc[rs[d] + pos] = src[e];
    }
}

// ---------------- tf32 tensor-core GEMM, smem-staged (R6 known-good) ----------
__device__ __forceinline__ unsigned f2tf(float x) {
    unsigned r;
    asm("cvt.rna.tf32.f32 %0, %1;" : "=r"(r) : "f"(x));
    return r;
}

template <bool HALF_OUT>
__global__ __launch_bounds__(256) void gemm_smem(
        const float* __restrict__ A, const float* __restrict__ W,
        void* __restrict__ Cv, int n, int K, int M) {
    __shared__ unsigned As[128][36];
    __shared__ unsigned Ws[32][72];
    int tid = threadIdx.x;
    int warp = tid >> 5, lane = tid & 31;
    int g = lane >> 2, t = lane & 3;
    int row0 = blockIdx.y * 128;
    int col0 = blockIdx.x * 64;

    float4 pa[4], pw[2];
    #pragma unroll
    for (int q = 0; q < 4; q++) {
        int j = tid + q * 256, r = row0 + (j >> 3), kq = j & 7;
        pa[q] = (r < n) ? *(const float4*)(A + (size_t)r * K + kq * 4)
                        : make_float4(0.f, 0.f, 0.f, 0.f);
    }
    #pragma unroll
    for (int q = 0; q < 2; q++) {
        int j = tid + q * 256, kk = j >> 4, cq = j & 15;
        pw[q] = *(const float4*)(W + (size_t)kk * M + col0 + cq * 4);
    }

    float acc[8][4];
    #pragma unroll
    for (int i = 0; i < 8; i++)
        #pragma unroll
        for (int j = 0; j < 4; j++) acc[i][j] = 0.f;

    int NP = K >> 5;
    for (int p = 0; p < NP; p++) {
        #pragma unroll
        for (int q = 0; q < 4; q++) {
            int j = tid + q * 256, r = j >> 3, kq = j & 7;
            uint4 u = make_uint4(f2tf(pa[q].x), f2tf(pa[q].y), f2tf(pa[q].z), f2tf(pa[q].w));
            *(uint4*)&As[r][kq * 4] = u;
        }
        #pragma unroll
        for (int q = 0; q < 2; q++) {
            int j = tid + q * 256, kk = j >> 4, cq = j & 15;
            uint4 u = make_uint4(f2tf(pw[q].x), f2tf(pw[q].y), f2tf(pw[q].z), f2tf(pw[q].w));
            *(uint4*)&Ws[kk][cq * 4] = u;
        }
        __syncthreads();

        if (p + 1 < NP) {
            int k0 = (p + 1) << 5;
            #pragma unroll
            for (int q = 0; q < 4; q++) {
                int j = tid + q * 256, r = row0 + (j >> 3), kq = j & 7;
                pa[q] = (r < n) ? *(const float4*)(A + (size_t)r * K + k0 + kq * 4)
                                : make_float4(0.f, 0.f, 0.f, 0.f);
            }
            #pragma unroll
            for (int q = 0; q < 2; q++) {
                int j = tid + q * 256, kk = j >> 4, cq = j & 15;
                pw[q] = *(const float4*)(W + (size_t)(k0 + kk) * M + col0 + cq * 4);
            }
        }

        int rb = warp << 4;
        #pragma unroll
        for (int ks = 0; ks < 4; ks++) {
            int kk = ks * 8 + t;
            unsigned a0 = As[rb + g][kk],     a1 = As[rb + g + 8][kk];
            unsigned a2 = As[rb + g][kk + 4], a3 = As[rb + g + 8][kk + 4];
            #pragma unroll
            for (int nt = 0; nt < 8; nt++) {
                unsigned b0 = Ws[kk][nt * 8 + g];
                unsigned b1 = Ws[kk + 4][nt * 8 + g];
                asm("mma.sync.aligned.m16n8k8.row.col.f32.tf32.tf32.f32 "
                    "{%0,%1,%2,%3}, {%4,%5,%6,%7}, {%8,%9}, {%0,%1,%2,%3};"
                    : "+f"(acc[nt][0]), "+f"(acc[nt][1]), "+f"(acc[nt][2]), "+f"(acc[nt][3])
                    : "r"(a0), "r"(a1), "r"(a2), "r"(a3), "r"(b0), "r"(b1));
            }
        }
        __syncthreads();
    }

    int r0 = row0 + (warp << 4) + g, r1 = r0 + 8;
    #pragma unroll
    for (int nt = 0; nt < 8; nt++) {
        int c = col0 + nt * 8 + 2 * t;
        if (HALF_OUT) {
            __half2* C = (__half2*)Cv;
            if (r0 < n) C[((size_t)r0 * M + c) >> 1] = __floats2half2_rn(acc[nt][0], acc[nt][1]);
            if (r1 < n) C[((size_t)r1 * M + c) >> 1] = __floats2half2_rn(acc[nt][2], acc[nt][3]);
        } else {
            float* C = (float*)Cv;
            if (r0 < n) *(float2*)(C + (size_t)r0 * M + c) = make_float2(acc[nt][0], acc[nt][1]);
            if (r1 < n) *(float2*)(C + (size_t)r1 * M + c) = make_float2(acc[nt][2], acc[nt][3]);
        }
    }
}

// ---------------- pack W1 and [W_sage_l | W_sage_r] ----------------
__global__ void pack_kernel(const float* __restrict__ W1, const float* __restrict__ Wl,
                            const float* __restrict__ Wr, float* __restrict__ W1p,
                            float* __restrict__ Wsp) {
    int i = blockIdx.x * 256 + threadIdx.x;
    if (i < 64 * 128) {
        int k = i >> 7, m = i & 127;
        W1p[i] = (m < 64) ? W1[k * 64 + m] : W1[(64 + k) * 64 + (m - 64)];
    }
    int j = i - 64 * 128;
    if (j >= 0 && j < 256 * 128) {
        int k = j >> 7, m = j & 127;
        Wsp[j] = (m < 64) ? Wl[k * 64 + m] : Wr[k * 64 + (m - 64)];
    }
}

// ---------------- GCN aggregation (warp per node, float2 lanes) ----------------
__global__ void gcn_agg_kernel(const float* __restrict__ h0, const float* __restrict__ b_gcn,
                               const int* __restrict__ rs, const int* __restrict__ csrc,
                               const float* __restrict__ dinv, float* __restrict__ hout) {
    int node = (blockIdx.x * blockDim.x + threadIdx.x) >> 5;
    int lane = threadIdx.x & 31;
    if (node >= NN) return;
    int beg = rs[node], end = rs[node + 1];
    float dinv_d = dinv[node];
    const float2* H = (const float2*)h0;
    float ax = 0.f, ay = 0.f;
    for (int p = beg; p < end; p++) {
        int s = csrc[p];
        float ds = dinv[s];
        float2 hv = H[(size_t)s * 32 + lane];
        ax += hv.x * ds; ay += hv.y * ds;
    }
    float2 hd = H[(size_t)node * 32 + lane];
    ax = (ax + hd.x * dinv_d) * dinv_d;
    ay = (ay + hd.y * dinv_d) * dinv_d;
    float2 b = ((const float2*)b_gcn)[lane];
    float2 o;
    o.x = fmaxf(ax + b.x, 0.f);
    o.y = fmaxf(ay + b.y, 0.f);
    ((float2*)hout)[(size_t)node * 32 + lane] = o;
}

// ---------------- attention logits from fp16 g ----------------
__global__ void att_kernel(const __half* __restrict__ ghp,
                           const float* __restrict__ att_src,
                           const float* __restrict__ att_dst,
                           float* __restrict__ as_, float* __restrict__ ad_) {
    int node = (blockIdx.x * blockDim.x + threadIdx.x) >> 5;
    int lane = threadIdx.x & 31;
    if (node >= NN) return;
    const float4* GH = (const float4*)ghp;
    float4 raw = GH[(size_t)node * 32 + lane];
    const __half2* hp = (const __half2*)&raw;
    float4 wsa = ((const float4*)att_src)[2 * lane];
    float4 wsb = ((const float4*)att_src)[2 * lane + 1];
    float4 wda = ((const float4*)att_dst)[2 * lane];
    float4 wdb = ((const float4*)att_dst)[2 * lane + 1];
    float2 f0 = __half22float2(hp[0]), f1 = __half22float2(hp[1]);
    float2 f2 = __half22float2(hp[2]), f3 = __half22float2(hp[3]);
    float ps = f0.x * wsa.x + f0.y * wsa.y + f1.x * wsa.z + f1.y * wsa.w
             + f2.x * wsb.x + f2.y * wsb.y + f3.x * wsb.z + f3.y * wsb.w;
    float pd = f0.x * wda.x + f0.y * wda.y + f1.x * wda.z + f1.y * wda.w
             + f2.x * wdb.x + f2.y * wdb.y + f3.x * wdb.z + f3.y * wdb.w;
    #pragma unroll
    for (int off = 4; off; off >>= 1) {
        ps += __shfl_down_sync(0xffffffffu, ps, off, 8);
        pd += __shfl_down_sync(0xffffffffu, pd, off, 8);
    }
    if ((lane & 7) == 0) {
        int head = lane >> 3;
        as_[node * 4 + head] = ps;
        ad_[node * 4 + head] = pd;
    }
}

// ---------------- alpha precompute: softmax weights out of the gather ----------
// Warp per node, lanes parallel over edges. Writes unnormalized weights per
// edge (float4), self weight, and 1/z per node. 4 expf per 32 edges per
// instruction instead of 1 expf + 4 SHFL per edge in the gather loop.
__global__ void alpha_kernel(const float* __restrict__ as_,
                             const float* __restrict__ ad_,
                             const int* __restrict__ rs,
                             const int* __restrict__ csrc,
                             float4* __restrict__ alpha,
                             float4* __restrict__ wself,
                             float4* __restrict__ zinv) {
    int node = (blockIdx.x * blockDim.x + threadIdx.x) >> 5;
    int lane = threadIdx.x & 31;
    if (node >= NN) return;
    int beg = rs[node], end = rs[node + 1];
    float4 adv = *(const float4*)(ad_ + 4 * node);
    float4 asd = *(const float4*)(as_ + 4 * node);
    float e0s = lrelu(asd.x + adv.x), e1s = lrelu(asd.y + adv.y);
    float e2s = lrelu(asd.z + adv.z), e3s = lrelu(asd.w + adv.w);
    float m0 = e0s, m1 = e1s, m2 = e2s, m3 = e3s;
    for (int p = beg + lane; p < end; p += 32) {
        int s = csrc[p];
        float4 av = *(const float4*)(as_ + 4 * s);
        m0 = fmaxf(m0, lrelu(av.x + adv.x));
        m1 = fmaxf(m1, lrelu(av.y + adv.y));
        m2 = fmaxf(m2, lrelu(av.z + adv.z));
        m3 = fmaxf(m3, lrelu(av.w + adv.w));
    }
    #pragma unroll
    for (int off = 16; off; off >>= 1) {
        m0 = fmaxf(m0, __shfl_xor_sync(0xffffffffu, m0, off));
        m1 = fmaxf(m1, __shfl_xor_sync(0xffffffffu, m1, off));
        m2 = fmaxf(m2, __shfl_xor_sync(0xffffffffu, m2, off));
        m3 = fmaxf(m3, __shfl_xor_sync(0xffffffffu, m3, off));
    }
    float z0 = 0.f, z1 = 0.f, z2 = 0.f, z3 = 0.f;
    for (int p = beg + lane; p < end; p += 32) {
        int s = csrc[p];
        float4 av = *(const float4*)(as_ + 4 * s);
        float w0 = expf(lrelu(av.x + adv.x) - m0);
        float w1 = expf(lrelu(av.y + adv.y) - m1);
        float w2 = expf(lrelu(av.z + adv.z) - m2);
        float w3 = expf(lrelu(av.w + adv.w) - m3);
        alpha[p] = make_float4(w0, w1, w2, w3);
        z0 += w0; z1 += w1; z2 += w2; z3 += w3;
    }
    #pragma unroll
    for (int off = 16; off; off >>= 1) {
        z0 += __shfl_xor_sync(0xffffffffu, z0, off);
        z1 += __shfl_xor_sync(0xffffffffu, z1, off);
        z2 += __shfl_xor_sync(0xffffffffu, z2, off);
        z3 += __shfl_xor_sync(0xffffffffu, z3, off);
    }
    if (lane == 0) {
        float w0s = expf(e0s - m0), w1s = expf(e1s - m1);
        float w2s = expf(e2s - m2), w3s = expf(e3s - m3);
        wself[node] = make_float4(w0s, w1s, w2s, w3s);
        zinv[node] = make_float4(1.f / (z0 + w0s + 1e-16f), 1.f / (z1 + w1s + 1e-16f),
                                 1.f / (z2 + w2s + 1e-16f), 1.f / (z3 + w3s + 1e-16f));
    }
}

// ---------------- GAT aggregation (pure gather with precomputed alpha) --------
__global__ void gat_agg_kernel(const __half* __restrict__ ghp,
                               const float4* __restrict__ alpha,
                               const float4* __restrict__ wself,
                               const float4* __restrict__ zinv,
                               const float* __restrict__ b_gat,
                               const int* __restrict__ rs,
                               const int* __restrict__ csrc,
                               float* __restrict__ g2) {
    int node = (blockIdx.x * blockDim.x + threadIdx.x) >> 5;
    int lane = threadIdx.x & 31;
    if (node >= NN) return;
    int beg = rs[node], end = rs[node + 1];
    int head = lane >> 3;               // lane covers cols [8*lane, 8*lane+8)
    float acc[8] = {0.f, 0.f, 0.f, 0.f, 0.f, 0.f, 0.f, 0.f};
    const float4* GH = (const float4*)ghp;
    for (int p = beg; p < end; p++) {
        int s = csrc[p];
        float4 a = alpha[p];
        float w = head == 0 ? a.x : head == 1 ? a.y : head == 2 ? a.z : a.w;
        float4 raw = GH[(size_t)s * 32 + lane];
        const __half2* hp = (const __half2*)&raw;
        #pragma unroll
        for (int j = 0; j < 4; j++) {
            float2 f = __half22float2(hp[j]);
            acc[2 * j]     += f.x * w;
            acc[2 * j + 1] += f.y * w;
        }
    }
    {   // self loop
        float4 ws = wself[node];
        float w = head == 0 ? ws.x : head == 1 ? ws.y : head == 2 ? ws.z : ws.w;
        float4 raw = GH[(size_t)node * 32 + lane];
        const __half2* hp = (const __half2*)&raw;
        #pragma unroll
        for (int j = 0; j < 4; j++) {
            float2 f = __half22float2(hp[j]);
            acc[2 * j]     += f.x * w;
            acc[2 * j + 1] += f.y * w;
        }
    }
    float4 zi = zinv[node];
    float inv = head == 0 ? zi.x : head == 1 ? zi.y : head == 2 ? zi.z : zi.w;
    float4 ba = ((const float4*)b_gat)[2 * lane];
    float4 bb = ((const float4*)b_gat)[2 * lane + 1];
    float4 oa, ob;
    oa.x = fmaxf(acc[0] * inv + ba.x, 0.f);
    oa.y = fmaxf(acc[1] * inv + ba.y, 0.f);
    oa.z = fmaxf(acc[2] * inv + ba.z, 0.f);
    oa.w = fmaxf(acc[3] * inv + ba.w, 0.f);
    ob.x = fmaxf(acc[4] * inv + bb.x, 0.f);
    ob.y = fmaxf(acc[5] * inv + bb.y, 0.f);
    ob.z = fmaxf(acc[6] * inv + bb.z, 0.f);
    ob.w = fmaxf(acc[7] * inv + bb.w, 0.f);
    ((float4*)g2)[(size_t)node * 64 + 2 * lane]     = oa;
    ((float4*)g2)[(size_t)node * 64 + 2 * lane + 1] = ob;
}

// ---------------- SAGE fused: s = relu(sum(y[nbr])/cnt + r + b) ----------------
__global__ void sage_fuse_kernel(const float* __restrict__ yr,
                                 const float* __restrict__ b_sage,
                                 const int* __restrict__ rs, const int* __restrict__ csrc,
                                 float* __restrict__ s) {
    int node = (blockIdx.x * blockDim.x + threadIdx.x) >> 5;
    int lane = threadIdx.x & 31;
    if (node >= NN) return;
    int beg = rs[node], end = rs[node + 1];
    const float2* Y = (const float2*)yr;
    float ax = 0.f, ay = 0.f;
    for (int p = beg; p < end; p++) {
        int sn = csrc[p];
        float2 yv = Y[(size_t)sn * 64 + lane];
        ax += yv.x; ay += yv.y;
    }
    float inv = 1.f / fmaxf((float)(end - beg), 1.f);
    float2 rv = Y[(size_t)node * 64 + 32 + lane];
    float2 bv = ((const float2*)b_sage)[lane];
    float2 o;
    o.x = fmaxf(ax * inv + rv.x + bv.x, 0.f);
    o.y = fmaxf(ay * inv + rv.y + bv.y, 0.f);
    ((float2*)s)[(size_t)node * 32 + lane] = o;
}

// ---------------- edge MLP + sigmoid (16 lanes per edge, fp32 uv) --------------
__global__ void edge_kernel(const int* __restrict__ src, const int* __restrict__ dst,
                            const float* __restrict__ uv, const float* __restrict__ b1,
                            const float* __restrict__ W2, const float* __restrict__ b2,
                            float* __restrict__ out) {
    int idx = blockIdx.x * blockDim.x + threadIdx.x;
    int e = idx >> 4;
    int l = idx & 15;
    if (e >= EE) return;
    int si = src[e], di = dst[e];
    const float4* UV = (const float4*)uv;
    float4 uu = UV[(size_t)si * 32 + l];
    float4 vv = UV[(size_t)di * 32 + 16 + l];
    float4 bb = ((const float4*)b1)[l];
    float4 ww = ((const float4*)W2)[l];
    float p = fmaxf(uu.x + vv.x + bb.x, 0.f) * ww.x
            + fmaxf(uu.y + vv.y + bb.y, 0.f) * ww.y
            + fmaxf(uu.z + vv.z + bb.z, 0.f) * ww.z
            + fmaxf(uu.w + vv.w + bb.w, 0.f) * ww.w;
    #pragma unroll
    for (int off = 8; off; off >>= 1) p += __shfl_xor_sync(0xffffffffu, p, off);
    if (l == 0) out[e] = 1.f / (1.f + expf(-(p + b2[0])));
}

// ---------------- launch ----------------
extern "C" void kernel_launch(void* const* d_in, const int* in_sizes, int n_in,
                              void* d_out, int out_size) {
    const float* x        = (const float*)d_in[0];
    const int*   ei       = (const int*)  d_in[1];
    const float* W_gcn    = (const float*)d_in[2];
    const float* b_gcn    = (const float*)d_in[3];
    const float* W_gat    = (const float*)d_in[4];
    const float* att_src  = (const float*)d_in[5];
    const float* att_dst  = (const float*)d_in[6];
    const float* b_gat    = (const float*)d_in[7];
    const float* W_sage_l = (const float*)d_in[8];
    const float* b_sage   = (const float*)d_in[9];
    const float* W_sage_r = (const float*)d_in[10];
    const float* W1       = (const float*)d_in[11];
    const float* b1       = (const float*)d_in[12];
    const float* W2       = (const float*)d_in[13];
    const float* b2       = (const float*)d_in[14];
    float* out = (float*)d_out;
    const int* src = ei;
    const int* dst = ei + EE;

    float *h0, *h, *g2, *yr, *s, *uv, *w1p, *wsp, *as_, *ad_, *dinv;
    float *alpha, *wself, *zinv;
    __half* gh;
    int *cnt, *cur, *rs, *bsum, *csrc;
    cudaGetSymbolAddress((void**)&h0,  g_h0);
    cudaGetSymbolAddress((void**)&h,   g_h);
    cudaGetSymbolAddress((void**)&gh,  g_gh);
    cudaGetSymbolAddress((void**)&g2,  g_g2);
    cudaGetSymbolAddress((void**)&yr,  g_yr);
    cudaGetSymbolAddress((void**)&s,   g_s);
    cudaGetSymbolAddress((void**)&uv,  g_uv);
    cudaGetSymbolAddress((void**)&w1p, g_w1p);
    cudaGetSymbolAddress((void**)&wsp, g_wsp);
    cudaGetSymbolAddress((void**)&as_, g_as);
    cudaGetSymbolAddress((void**)&ad_, g_ad);
    cudaGetSymbolAddress((void**)&alpha, g_alpha);
    cudaGetSymbolAddress((void**)&wself, g_wself);
    cudaGetSymbolAddress((void**)&zinv,  g_zinv);
    cudaGetSymbolAddress((void**)&dinv, g_dinv);
    cudaGetSymbolAddress((void**)&cnt, g_cnt);
    cudaGetSymbolAddress((void**)&cur, g_cur);
    cudaGetSymbolAddress((void**)&rs,  g_rs);
    cudaGetSymbolAddress((void**)&bsum, g_bsum);
    cudaGetSymbolAddress((void**)&csrc, g_csrc);

    const int NB_NODE = (NN + 255) / 256;          // 196
    const int NB_EDGE = (EE + 255) / 256;          // 3125
    const int NB_E4   = (EE / 4 + 255) / 256;      // 782
    const int NB_NW   = (NN * 32 + 255) / 256;     // 6250
    const int NB_E16  = (EE * 16 + 255) / 256;     // 50000
    const int NT128   = (NN + 127) / 128;          // 391

    // 1-3: CSR counts (GEMM placed 4th so the profiler slot lands on it)
    init_kernel<<<NB_NODE, 256>>>(cnt, cur);
    hist_kernel<<<NB_E4, 256>>>(dst, cnt);
    blocksum_kernel<<<NBLK, 256>>>(cnt, bsum);
    // 4: GCN GEMM (profiled control)
    gemm_smem<false><<<dim3(1, NT128), 256>>>(x, W_gcn, h0, NN, 128, 64);
    // 5-8: finish CSR + packs
    scanb_kernel<<<1, 256>>>(bsum);
    rs_kernel<<<NBLK, 256>>>(cnt, bsum, rs, dinv);
    fill_kernel<<<NB_EDGE, 256>>>(src, dst, rs, cur, csrc);
    pack_kernel<<<(64 * 128 + 256 * 128 + 255) / 256, 256>>>(W1, W_sage_l, W_sage_r, w1p, wsp);

    // GCN aggregate
    gcn_agg_kernel<<<NB_NW, 256>>>(h0, b_gcn, rs, csrc, dinv, h);

    // GAT: GEMM (fp16 g) -> logits -> alpha precompute -> pure gather
    gemm_smem<true><<<dim3(4, NT128), 256>>>(h, W_gat, gh, NN, 64, 256);
    att_kernel<<<NB_NW, 256>>>(gh, att_src, att_dst, as_, ad_);
    alpha_kernel<<<NB_NW, 256>>>(as_, ad_, rs, csrc,
                                 (float4*)alpha, (float4*)wself, (float4*)zinv);
    gat_agg_kernel<<<NB_NW, 256>>>(gh, (const float4*)alpha, (const float4*)wself,
                                   (const float4*)zinv, b_gat, rs, csrc, g2);

    // SAGE: yr = g2 @ [Wl | Wr], then fused gather
    gemm_smem<false><<<dim3(2, NT128), 256>>>(g2, wsp, yr, NN, 256, 128);
    sage_fuse_kernel<<<NB_NW, 256>>>(yr, b_sage, rs, csrc, s);

    // edge MLP: uv = s @ W1p (fp32)
    gemm_smem<false><<<dim3(2, NT128), 256>>>(s, w1p, uv, NN, 64, 128);

    // per-edge: sigmoid(relu(u[src]+v[dst]+b1) . W2 + b2)
    edge_kernel<<<NB_E16, 256>>>(src, dst, uv, b1, W2, b2, out);
}